// round 7
// baseline (speedup 1.0000x reference)
#include <cuda_runtime.h>
#include <cuda_bf16.h>
#include <math.h>
#include <stdint.h>

#define BB 16
#define GG 4
#define CGc 64
#define HH 64
#define WW 64
#define HWs 4096
#define KK 9

// ---------------- scratch (static; no allocation) ----------------
__device__ float g_off[BB*GG*18*HWs];                 // offsets [bg][c=2k+j][h][w]
__device__ float g_owt[GG*CGc*KK*20];                 // off_w transposed: [g][ic][tap][c pad 20]
__device__ float g_xT [BB*GG*HWs*CGc];                // x transposed: [bg][pix][ic]  (67MB)
__device__ __nv_bfloat16 g_wbh[GG*KK*CGc*CGc];        // def_w bf16 hi, pre-SW128-swizzled rows [oc][ic]
__device__ __nv_bfloat16 g_wbl[GG*KK*CGc*CGc];        // def_w bf16 lo, same layout

#define SWZ128(off) ((off) ^ (((off) >> 3) & 0x70))

// ---------------- helpers ----------------
__device__ __forceinline__ uint32_t smem_u32(const void* p) {
    uint32_t a;
    asm("{ .reg .u64 t; cvta.to.shared.u64 t, %1; cvt.u32.u64 %0, t; }" : "=r"(a) : "l"(p));
    return a;
}
__device__ __forceinline__ void ldsm_x4(uint32_t* r, uint32_t addr) {
    asm volatile("ldmatrix.sync.aligned.m8n8.x4.shared.b16 {%0,%1,%2,%3}, [%4];"
        : "=r"(r[0]), "=r"(r[1]), "=r"(r[2]), "=r"(r[3]) : "r"(addr));
}
__device__ __forceinline__ void mma_bf16(float* d, const uint32_t* a, uint32_t b0, uint32_t b1) {
    asm volatile(
        "mma.sync.aligned.m16n8k16.row.col.f32.bf16.bf16.f32 "
        "{%0,%1,%2,%3}, {%4,%5,%6,%7}, {%8,%9}, {%0,%1,%2,%3};"
        : "+f"(d[0]), "+f"(d[1]), "+f"(d[2]), "+f"(d[3])
        : "r"(a[0]), "r"(a[1]), "r"(a[2]), "r"(a[3]), "r"(b0), "r"(b1));
}

// ---------------- prep: weight transforms ----------------
__global__ void prep_kernel(const float* __restrict__ off_w,
                            const float* __restrict__ def_w) {
    int idx = blockIdx.x * blockDim.x + threadIdx.x;
    const int n_w = GG*KK*CGc*CGc;    // 147456
    if (idx < n_w) {
        int ic = idx & 63;
        int oc = (idx >> 6) & 63;
        int gk = idx >> 12;           // g*9+k
        int k  = gk % KK;
        int g  = gk / KK;
        float w = def_w[((g*CGc + oc)*CGc + ic)*KK + k];
        __nv_bfloat16 hi = __float2bfloat16(w);
        float lo = w - __bfloat162float(hi);
        uint32_t sw = SWZ128((uint32_t)(oc*128 + ic*2));
        size_t base = (size_t)(g*KK + k) * CGc * CGc;
        g_wbh[base + sw/2] = hi;
        g_wbl[base + sw/2] = __float2bfloat16(lo);
    }
    const int n_owt = GG*CGc*KK*20;   // 46080
    if (idx < n_owt) {
        int c  = idx % 20;
        int t  = (idx / 20) % KK;
        int ic = (idx / 180) % CGc;
        int g  = idx / (180*CGc);
        g_owt[idx] = (c < 18) ? off_w[((g*18 + c)*CGc + ic)*KK + t] : 0.0f;
    }
}

// ---------------- transpose: x[bg][ic][pix] -> xT[bg][pix][ic] ----------------
// block = 256 threads, tile = 64 ic x 64 pix
__global__ void __launch_bounds__(256) transpose_kernel(const float* __restrict__ x) {
    __shared__ float tsm[64][65];
    int bg   = blockIdx.x >> 6;
    int pix0 = (blockIdx.x & 63) * 64;
    int tid  = threadIdx.x;

    const float* xb = x + (size_t)bg * CGc * HWs + pix0;
#pragma unroll
    for (int i = 0; i < 16; i++) {
        int e  = tid + i*256;
        int ic = e >> 6, p = e & 63;
        tsm[ic][p] = xb[ic*HWs + p];
    }
    __syncthreads();

    float* xo = g_xT + (size_t)bg * HWs * CGc + (size_t)pix0 * CGc;
#pragma unroll
    for (int i = 0; i < 16; i++) {
        int e  = tid + i*256;
        int p  = e >> 6, ic = e & 63;
        xo[p*CGc + ic] = tsm[ic][p];
    }
}

// ---------------- offset conv: 64 -> 18, 3x3 (scalar fp32) ----------------
extern __shared__ float smem1[];
__global__ void __launch_bounds__(256) offset_kernel(const float* __restrict__ x,
                                                     const float* __restrict__ off_b) {
    float* sx = smem1;              // 3*64*64 floats
    float* sw = smem1 + 12288;      // 64*9*20 floats

    int bid = blockIdx.x;
    int h = bid & 63;
    int g = (bid >> 6) & 3;
    int b = bid >> 8;
    int tid = threadIdx.x;

    const float* owt = g_owt + g*CGc*KK*20;
    for (int i = tid; i < CGc*KK*20; i += 256) sw[i] = owt[i];

    const float* xb = x + (size_t)(b*GG + g) * CGc * HWs;
    for (int i = tid; i < 3*CGc*WW; i += 256) {
        int ky = i >> 12;
        int ic = (i >> 6) & 63;
        int w  = i & 63;
        int row = h - 1 + ky;
        sx[i] = (row >= 0 && row < HH) ? xb[ic*HWs + row*WW + w] : 0.0f;
    }
    __syncthreads();

    int w   = tid & 63;
    int sub = tid >> 6;

    float4 a4[5];
#pragma unroll
    for (int q = 0; q < 5; q++) a4[q] = make_float4(0.f,0.f,0.f,0.f);

#pragma unroll
    for (int ky = 0; ky < 3; ky++) {
        const float* sxk = sx + ky*4096;
        for (int ic = sub*16; ic < sub*16 + 16; ic++) {
            const float* xr = sxk + ic*64;
            float xv0 = (w > 0)  ? xr[w-1] : 0.0f;
            float xv1 = xr[w];
            float xv2 = (w < 63) ? xr[w+1] : 0.0f;
            const float4* wp = (const float4*)(sw + (ic*KK + ky*3)*20);
#pragma unroll
            for (int kx = 0; kx < 3; kx++) {
                float xs = (kx == 0) ? xv0 : ((kx == 1) ? xv1 : xv2);
#pragma unroll
                for (int q = 0; q < 5; q++) {
                    float4 wv = wp[kx*5 + q];
                    a4[q].x += wv.x * xs;
                    a4[q].y += wv.y * xs;
                    a4[q].z += wv.z * xs;
                    a4[q].w += wv.w * xs;
                }
            }
        }
    }
    __syncthreads();

    float* red = sx;
#pragma unroll
    for (int q = 0; q < 5; q++) {
        int c = q*4;
        if (c+0 < 18) red[(sub*18 + c+0)*64 + w] = a4[q].x;
        if (c+1 < 18) red[(sub*18 + c+1)*64 + w] = a4[q].y;
        if (c+2 < 18) red[(sub*18 + c+2)*64 + w] = a4[q].z;
        if (c+3 < 18) red[(sub*18 + c+3)*64 + w] = a4[q].w;
    }
    __syncthreads();

    for (int i = tid; i < 18*64; i += 256) {
        int c = i >> 6, ww = i & 63;
        float s = red[(0*18 + c)*64 + ww] + red[(1*18 + c)*64 + ww]
                + red[(2*18 + c)*64 + ww] + red[(3*18 + c)*64 + ww]
                + off_b[g*18 + c];
        g_off[((size_t)(b*GG + g)*18 + c)*HWs + h*64 + ww] = s;
    }
}

// ---------------- deformable conv: mma.sync bf16x2 GEMM ----------------
// block = (b, g, hblk of 2 rows); 128 threads (4 warps)
// M=128 (2h x 64w), N=64 oc, K per tap = 64 ic, 9 taps
#define SM_SHI  0        // S hi [128 x 64] bf16 SW128 : 16384 B
#define SM_SLO  16384    // S lo                       : 16384 B
#define SM_WHI  32768    // W hi [64 x 64] bf16 SW128  :  8192 B
#define SM_WLO  40960    // W lo                       :  8192 B
#define SM_TOTAL 49152

extern __shared__ char smem2[];
__global__ void __launch_bounds__(128) deform_kernel(const float* __restrict__ def_b,
                                                     float* __restrict__ out) {
    char* sm = smem2;
    uint32_t smem_base = smem_u32(sm);
    int tid  = threadIdx.x;
    int wid  = tid >> 5;
    int lane = tid & 31;

    int bid  = blockIdx.x;
    int hblk = bid & 31;
    int g    = (bid >> 5) & 3;
    int b    = bid >> 7;
    int bg   = b*GG + g;

    int m    = tid;            // S-tile row this thread gathers
    int r    = m >> 6;
    int wpos = m & 63;
    int h    = hblk*2 + r;

    const float* xTb  = g_xT + (size_t)bg * HWs * CGc;
    const float* offp = g_off + (size_t)bg * 18 * HWs + h*64 + wpos;

    char* shi_row = sm + SM_SHI + m*128;
    char* slo_row = sm + SM_SLO + m*128;
    uint32_t swz = (uint32_t)((m & 7) << 4);

    float acc[2][8][4];
#pragma unroll
    for (int mt = 0; mt < 2; mt++)
#pragma unroll
        for (int nt = 0; nt < 8; nt++)
#pragma unroll
            for (int q = 0; q < 4; q++) acc[mt][nt][q] = 0.0f;

    // per-thread ldmatrix row/col components
    int a_row0   = wid*32 + (lane & 15);        // + mt*16
    int ab_colsl = (lane >> 4) << 4;            // 0 or 16 bytes
    int b_row0   = ((lane >> 3) & 1)*8 + (lane & 7);  // + ntp*16

    for (int k = 0; k < KK; k++) {
        // ---- fill W tiles (pre-swizzled gmem -> linear copy) ----
        {
            const uint4* s1 = (const uint4*)(g_wbh + (size_t)(g*KK + k) * CGc * CGc);
            const uint4* s2 = (const uint4*)(g_wbl + (size_t)(g*KK + k) * CGc * CGc);
            uint4* d1 = (uint4*)(sm + SM_WHI);
            uint4* d2 = (uint4*)(sm + SM_WLO);
#pragma unroll
            for (int i = 0; i < 4; i++) {
                d1[tid + i*128] = s1[tid + i*128];
                d2[tid + i*128] = s2[tid + i*128];
            }
        }

        // ---- per-thread bilinear corner precompute ----
        float dy = __ldg(offp + (2*k    )*HWs);
        float dx = __ldg(offp + (2*k + 1)*HWs);
        float py = dy + (float)(k/3 - 1) + (float)h;
        float px = dx + (float)(k%3 - 1) + (float)wpos;
        float fy = floorf(py), fx = floorf(px);
        float wy = py - fy,    wx = px - fx;
        int y0 = (int)fy, x0 = (int)fx;
        int y1 = y0 + 1,  x1 = x0 + 1;
        float vy0 = (y0 >= 0 && y0 < HH) ? 1.f : 0.f;
        float vy1 = (y1 >= 0 && y1 < HH) ? 1.f : 0.f;
        float vx0 = (x0 >= 0 && x0 < WW) ? 1.f : 0.f;
        float vx1 = (x1 >= 0 && x1 < WW) ? 1.f : 0.f;
        float c00 = (1.f-wy)*(1.f-wx) * vy0 * vx0;
        float c01 = (1.f-wy)*wx       * vy0 * vx1;
        float c10 = wy*(1.f-wx)       * vy1 * vx0;
        float c11 = wy*wx             * vy1 * vx1;
        int y0c = min(max(y0,0),HH-1), y1c = min(max(y1,0),HH-1);
        int x0c = min(max(x0,0),WW-1), x1c = min(max(x1,0),WW-1);
        // channels-last corner row pointers (64 contiguous floats each)
        const float* A = xTb + (size_t)(y0c*WW + x0c) * CGc;
        const float* Bp = xTb + (size_t)(y0c*WW + x1c) * CGc;
        const float* Cp = xTb + (size_t)(y1c*WW + x0c) * CGc;
        const float* D = xTb + (size_t)(y1c*WW + x1c) * CGc;

        // ---- gather (vectorized LDG.128) + bf16 hi/lo split into S tiles ----
#pragma unroll
        for (int icp = 0; icp < 8; icp++) {
            uint32_t hp[4], lp[4];
#pragma unroll
            for (int j = 0; j < 2; j++) {
                int ic4 = icp*8 + j*4;
                float4 av = __ldg((const float4*)(A  + ic4));
                float4 bv = __ldg((const float4*)(Bp + ic4));
                float4 cv = __ldg((const float4*)(Cp + ic4));
                float4 dv = __ldg((const float4*)(D  + ic4));
                float v0 = c00*av.x + c01*bv.x + c10*cv.x + c11*dv.x;
                float v1 = c00*av.y + c01*bv.y + c10*cv.y + c11*dv.y;
                float v2 = c00*av.z + c01*bv.z + c10*cv.z + c11*dv.z;
                float v3 = c00*av.w + c01*bv.w + c10*cv.w + c11*dv.w;
                uint32_t hh0, hh1;
                asm("cvt.rn.bf16x2.f32 %0, %1, %2;" : "=r"(hh0) : "f"(v1), "f"(v0));
                asm("cvt.rn.bf16x2.f32 %0, %1, %2;" : "=r"(hh1) : "f"(v3), "f"(v2));
                float l0 = v0 - __uint_as_float(hh0 << 16);
                float l1 = v1 - __uint_as_float(hh0 & 0xffff0000u);
                float l2 = v2 - __uint_as_float(hh1 << 16);
                float l3 = v3 - __uint_as_float(hh1 & 0xffff0000u);
                uint32_t ll0, ll1;
                asm("cvt.rn.bf16x2.f32 %0, %1, %2;" : "=r"(ll0) : "f"(l1), "f"(l0));
                asm("cvt.rn.bf16x2.f32 %0, %1, %2;" : "=r"(ll1) : "f"(l3), "f"(l2));
                hp[2*j] = hh0; hp[2*j+1] = hh1;
                lp[2*j] = ll0; lp[2*j+1] = ll1;
            }
            uint32_t off = ((uint32_t)(icp*16)) ^ swz;
            *(uint4*)(shi_row + off) = make_uint4(hp[0], hp[1], hp[2], hp[3]);
            *(uint4*)(slo_row + off) = make_uint4(lp[0], lp[1], lp[2], lp[3]);
        }
        __syncthreads();

        // ---- MMA: 4 k16-chunks x (2 m-tiles x 8 n-tiles) x 3 bf16x2 terms ----
#pragma unroll
        for (int kc = 0; kc < 4; kc++) {
            int colb = kc*32 + ab_colsl;
            uint32_t ah[2][4], al[2][4];
#pragma unroll
            for (int mt = 0; mt < 2; mt++) {
                int row = a_row0 + mt*16;
                uint32_t boff = (uint32_t)(row*128 + (colb ^ ((row & 7) << 4)));
                ldsm_x4(ah[mt], smem_base + SM_SHI + boff);
                ldsm_x4(al[mt], smem_base + SM_SLO + boff);
            }
#pragma unroll
            for (int ntp = 0; ntp < 4; ntp++) {
                int nrow = b_row0 + ntp*16;
                uint32_t boff = (uint32_t)(nrow*128 + (colb ^ ((nrow & 7) << 4)));
                uint32_t bh[4], bl[4];
                ldsm_x4(bh, smem_base + SM_WHI + boff);
                ldsm_x4(bl, smem_base + SM_WLO + boff);
#pragma unroll
                for (int mt = 0; mt < 2; mt++) {
                    mma_bf16(acc[mt][2*ntp  ], ah[mt], bh[0], bh[2]);
                    mma_bf16(acc[mt][2*ntp  ], ah[mt], bl[0], bl[2]);
                    mma_bf16(acc[mt][2*ntp  ], al[mt], bh[0], bh[2]);
                    mma_bf16(acc[mt][2*ntp+1], ah[mt], bh[1], bh[3]);
                    mma_bf16(acc[mt][2*ntp+1], ah[mt], bl[1], bl[3]);
                    mma_bf16(acc[mt][2*ntp+1], al[mt], bh[1], bh[3]);
                }
            }
        }
        __syncthreads();   // all warps done reading S/W before next tap overwrites
    }

    // ---- epilogue: fragment scatter to gmem (+bias) ----
    float* outg = out + (size_t)bg * CGc * HWs + hblk*2*64;
    const float* bbp = def_b + g*CGc;
#pragma unroll
    for (int mt = 0; mt < 2; mt++) {
        int row0  = wid*32 + mt*16 + (lane >> 2);
        int h_loc = row0 >> 6;
        int wp    = row0 & 63;
        float* p0 = outg + h_loc*64 + wp;
        float* p1 = p0 + 8;   // row0+8 stays in same 64-row band
#pragma unroll
        for (int nt = 0; nt < 8; nt++) {
            int oc0 = nt*8 + (lane & 3)*2;
            float bz0 = __ldg(bbp + oc0);
            float bz1 = __ldg(bbp + oc0 + 1);
            p0[(size_t)oc0*HWs]       = acc[mt][nt][0] + bz0;
            p0[(size_t)(oc0+1)*HWs]   = acc[mt][nt][1] + bz1;
            p1[(size_t)oc0*HWs]       = acc[mt][nt][2] + bz0;
            p1[(size_t)(oc0+1)*HWs]   = acc[mt][nt][3] + bz1;
        }
    }
}

// ---------------- launch ----------------
extern "C" void kernel_launch(void* const* d_in, const int* in_sizes, int n_in,
                              void* d_out, int out_size) {
    const float* x     = (const float*)d_in[0];
    const float* off_w = (const float*)d_in[1];
    const float* off_b = (const float*)d_in[2];
    const float* def_w = (const float*)d_in[3];
    const float* def_b = (const float*)d_in[4];
    float* out = (float*)d_out;

    cudaFuncSetAttribute(offset_kernel, cudaFuncAttributeMaxDynamicSharedMemorySize,
                         (12288 + 11520) * (int)sizeof(float));   // 95232 B
    cudaFuncSetAttribute(deform_kernel, cudaFuncAttributeMaxDynamicSharedMemorySize,
                         SM_TOTAL);                               // 49152 B

    prep_kernel<<<(GG*KK*CGc*CGc + 255) / 256, 256>>>(off_w, def_w);
    transpose_kernel<<<BB*GG*64, 256>>>(x);
    offset_kernel<<<BB*GG*HH, 256, (12288 + 11520) * sizeof(float)>>>(x, off_b);
    deform_kernel<<<BB*GG*(HH/2), 128, SM_TOTAL>>>(def_b, out);
}

// round 9
// speedup vs baseline: 1.2667x; 1.2667x over previous
#include <cuda_runtime.h>
#include <cuda_bf16.h>
#include <math.h>
#include <stdint.h>

#define BB 16
#define GG 4
#define CGc 64
#define HH 64
#define WW 64
#define HWs 4096
#define KK 9

// ---------------- scratch (static; no allocation) ----------------
__device__ float g_off[BB*GG*18*HWs];                 // offsets [bg][c=2k+j][h][w]
__device__ float g_owt[GG*CGc*KK*20];                 // off_w transposed: [g][ic][tap][c pad 20]
__device__ float2 g_xP[BB*GG*CGc*HWs];                // x pairs: [bg][ic][y][x] = (v[x], v[x+1])  (134MB)
__device__ __nv_bfloat16 g_wbh[GG*KK*CGc*CGc];        // def_w bf16 hi, pre-SW128-swizzled rows [oc][ic]
__device__ __nv_bfloat16 g_wbl[GG*KK*CGc*CGc];        // def_w bf16 lo, same layout

#define SWZ128(off) ((off) ^ (((off) >> 3) & 0x70))

// ---------------- helpers ----------------
__device__ __forceinline__ uint32_t smem_u32(const void* p) {
    uint32_t a;
    asm("{ .reg .u64 t; cvta.to.shared.u64 t, %1; cvt.u32.u64 %0, t; }" : "=r"(a) : "l"(p));
    return a;
}
__device__ __forceinline__ void ldsm_x4(uint32_t* r, uint32_t addr) {
    asm volatile("ldmatrix.sync.aligned.m8n8.x4.shared.b16 {%0,%1,%2,%3}, [%4];"
        : "=r"(r[0]), "=r"(r[1]), "=r"(r[2]), "=r"(r[3]) : "r"(addr));
}
__device__ __forceinline__ void mma_bf16(float* d, const uint32_t* a, uint32_t b0, uint32_t b1) {
    asm volatile(
        "mma.sync.aligned.m16n8k16.row.col.f32.bf16.bf16.f32 "
        "{%0,%1,%2,%3}, {%4,%5,%6,%7}, {%8,%9}, {%0,%1,%2,%3};"
        : "+f"(d[0]), "+f"(d[1]), "+f"(d[2]), "+f"(d[3])
        : "r"(a[0]), "r"(a[1]), "r"(a[2]), "r"(a[3]), "r"(b0), "r"(b1));
}

// ---------------- prep: weight transforms ----------------
__global__ void prep_kernel(const float* __restrict__ off_w,
                            const float* __restrict__ def_w) {
    int idx = blockIdx.x * blockDim.x + threadIdx.x;
    const int n_w = GG*KK*CGc*CGc;    // 147456
    if (idx < n_w) {
        int ic = idx & 63;
        int oc = (idx >> 6) & 63;
        int gk = idx >> 12;           // g*9+k
        int k  = gk % KK;
        int g  = gk / KK;
        float w = def_w[((g*CGc + oc)*CGc + ic)*KK + k];
        __nv_bfloat16 hi = __float2bfloat16(w);
        float lo = w - __bfloat162float(hi);
        uint32_t sw = SWZ128((uint32_t)(oc*128 + ic*2));
        size_t base = (size_t)(g*KK + k) * CGc * CGc;
        g_wbh[base + sw/2] = hi;
        g_wbl[base + sw/2] = __float2bfloat16(lo);
    }
    const int n_owt = GG*CGc*KK*20;   // 46080
    if (idx < n_owt) {
        int c  = idx % 20;
        int t  = (idx / 20) % KK;
        int ic = (idx / 180) % CGc;
        int g  = idx / (180*CGc);
        g_owt[idx] = (c < 18) ? off_w[((g*18 + c)*CGc + ic)*KK + t] : 0.0f;
    }
}

// ---------------- pair build: xP[i] = (x[i], x[i+1 or clamp]) ----------------
__global__ void __launch_bounds__(256) pair_kernel(const float* __restrict__ x) {
    size_t i = (size_t)blockIdx.x * 256 + threadIdx.x;   // over BB*GG*CGc*HWs
    int xc = (int)(i & 63);
    float v  = x[i];
    float vn = (xc < 63) ? x[i + 1] : v;
    g_xP[i] = make_float2(v, vn);
}

// ---------------- offset conv: 64 -> 18, 3x3 (scalar fp32) ----------------
extern __shared__ float smem1[];
__global__ void __launch_bounds__(256) offset_kernel(const float* __restrict__ x,
                                                     const float* __restrict__ off_b) {
    float* sx = smem1;              // 3*64*64 floats
    float* sw = smem1 + 12288;      // 64*9*20 floats

    int bid = blockIdx.x;
    int h = bid & 63;
    int g = (bid >> 6) & 3;
    int b = bid >> 8;
    int tid = threadIdx.x;

    const float* owt = g_owt + g*CGc*KK*20;
    for (int i = tid; i < CGc*KK*20; i += 256) sw[i] = owt[i];

    const float* xb = x + (size_t)(b*GG + g) * CGc * HWs;
    for (int i = tid; i < 3*CGc*WW; i += 256) {
        int ky = i >> 12;
        int ic = (i >> 6) & 63;
        int w  = i & 63;
        int row = h - 1 + ky;
        sx[i] = (row >= 0 && row < HH) ? xb[ic*HWs + row*WW + w] : 0.0f;
    }
    __syncthreads();

    int w   = tid & 63;
    int sub = tid >> 6;

    float4 a4[5];
#pragma unroll
    for (int q = 0; q < 5; q++) a4[q] = make_float4(0.f,0.f,0.f,0.f);

#pragma unroll
    for (int ky = 0; ky < 3; ky++) {
        const float* sxk = sx + ky*4096;
        for (int ic = sub*16; ic < sub*16 + 16; ic++) {
            const float* xr = sxk + ic*64;
            float xv0 = (w > 0)  ? xr[w-1] : 0.0f;
            float xv1 = xr[w];
            float xv2 = (w < 63) ? xr[w+1] : 0.0f;
            const float4* wp = (const float4*)(sw + (ic*KK + ky*3)*20);
#pragma unroll
            for (int kx = 0; kx < 3; kx++) {
                float xs = (kx == 0) ? xv0 : ((kx == 1) ? xv1 : xv2);
#pragma unroll
                for (int q = 0; q < 5; q++) {
                    float4 wv = wp[kx*5 + q];
                    a4[q].x += wv.x * xs;
                    a4[q].y += wv.y * xs;
                    a4[q].z += wv.z * xs;
                    a4[q].w += wv.w * xs;
                }
            }
        }
    }
    __syncthreads();

    float* red = sx;
#pragma unroll
    for (int q = 0; q < 5; q++) {
        int c = q*4;
        if (c+0 < 18) red[(sub*18 + c+0)*64 + w] = a4[q].x;
        if (c+1 < 18) red[(sub*18 + c+1)*64 + w] = a4[q].y;
        if (c+2 < 18) red[(sub*18 + c+2)*64 + w] = a4[q].z;
        if (c+3 < 18) red[(sub*18 + c+3)*64 + w] = a4[q].w;
    }
    __syncthreads();

    for (int i = tid; i < 18*64; i += 256) {
        int c = i >> 6, ww = i & 63;
        float s = red[(0*18 + c)*64 + ww] + red[(1*18 + c)*64 + ww]
                + red[(2*18 + c)*64 + ww] + red[(3*18 + c)*64 + ww]
                + off_b[g*18 + c];
        g_off[((size_t)(b*GG + g)*18 + c)*HWs + h*64 + ww] = s;
    }
}

// ---------------- deformable conv: mma.sync bf16x2 GEMM ----------------
// block = (b, g, hblk of 4 rows); 256 threads (8 warps)
// M=256 (4h x 64w), N=64 oc, K per tap = 64 ic, 9 taps
#define SM_SHI  0        // S hi [256 x 64] bf16 SW128 : 32768 B
#define SM_SLO  32768    // S lo                       : 32768 B
#define SM_WHI  65536    // W hi [64 x 64] bf16 SW128  :  8192 B
#define SM_WLO  73728    // W lo                       :  8192 B
#define SM_TOTAL 81920

extern __shared__ char smem2[];
__global__ void __launch_bounds__(256) deform_kernel(const float* __restrict__ def_b,
                                                     float* __restrict__ out) {
    char* sm = smem2;
    uint32_t smem_base = smem_u32(sm);
    int tid  = threadIdx.x;
    int wid  = tid >> 5;
    int lane = tid & 31;

    int bid  = blockIdx.x;
    int hblk = bid & 15;
    int g    = (bid >> 4) & 3;
    int b    = bid >> 6;
    int bg   = b*GG + g;

    int m    = tid;            // S-tile row this thread gathers
    int r    = m >> 6;         // 0..3
    int wpos = m & 63;
    int h    = hblk*4 + r;

    const float2* xPb = g_xP + (size_t)bg * CGc * HWs;
    const float* offp = g_off + (size_t)bg * 18 * HWs + h*64 + wpos;

    char* shi_row = sm + SM_SHI + m*128;
    char* slo_row = sm + SM_SLO + m*128;
    uint32_t swz = (uint32_t)((m & 7) << 4);

    float acc[2][8][4];
#pragma unroll
    for (int mt = 0; mt < 2; mt++)
#pragma unroll
        for (int nt = 0; nt < 8; nt++)
#pragma unroll
            for (int q = 0; q < 4; q++) acc[mt][nt][q] = 0.0f;

    // per-thread ldmatrix row/col components
    int a_row0   = wid*32 + (lane & 15);        // + mt*16
    int ab_colsl = (lane >> 4) << 4;            // 0 or 16 bytes
    int b_row0   = ((lane >> 3) & 1)*8 + (lane & 7);  // + ntp*16

    for (int k = 0; k < KK; k++) {
        // ---- fill W tiles (pre-swizzled gmem -> linear copy) ----
        {
            const uint4* s1 = (const uint4*)(g_wbh + (size_t)(g*KK + k) * CGc * CGc);
            const uint4* s2 = (const uint4*)(g_wbl + (size_t)(g*KK + k) * CGc * CGc);
            uint4* d1 = (uint4*)(sm + SM_WHI);
            uint4* d2 = (uint4*)(sm + SM_WLO);
#pragma unroll
            for (int i = 0; i < 2; i++) {
                d1[tid + i*256] = s1[tid + i*256];
                d2[tid + i*256] = s2[tid + i*256];
            }
        }

        // ---- per-thread bilinear corner precompute ----
        float dy = __ldg(offp + (2*k    )*HWs);
        float dx = __ldg(offp + (2*k + 1)*HWs);
        float py = dy + (float)(k/3 - 1) + (float)h;
        float px = dx + (float)(k%3 - 1) + (float)wpos;
        float fy = floorf(py), fx = floorf(px);
        float wy = py - fy,    wx = px - fx;
        int y0 = (int)fy, x0 = (int)fx;
        int y1 = y0 + 1,  x1 = x0 + 1;
        float vy0 = (y0 >= 0 && y0 < HH) ? 1.f : 0.f;
        float vy1 = (y1 >= 0 && y1 < HH) ? 1.f : 0.f;
        float vx0 = (x0 >= 0 && x0 < WW) ? 1.f : 0.f;
        float vx1 = (x1 >= 0 && x1 < WW) ? 1.f : 0.f;
        float c00 = (1.f-wy)*(1.f-wx) * vy0 * vx0;
        float c01 = (1.f-wy)*wx       * vy0 * vx1;
        float c10 = wy*(1.f-wx)       * vy1 * vx0;
        float c11 = wy*wx             * vy1 * vx1;
        // pair-load weight fix: pair at xl covers (xl, xl+1); when x0<0 the only
        // possibly-valid corner is x1(=0) = pair.x at xl=0 -> move BOTH row weights
        // onto the .x slot (this was the round-8 bug: c10/c11 were not swapped).
        if (x0 < 0) { c00 = c01; c01 = 0.f; c10 = c11; c11 = 0.f; }
        int xl  = min(max(x0,0),WW-1);
        int y0c = min(max(y0,0),HH-1), y1c = min(max(y1,0),HH-1);
        int o0 = y0c*WW + xl;
        int o1 = y1c*WW + xl;

        // ---- gather (paired LDG.64) + bf16 hi/lo split into S tiles ----
#pragma unroll
        for (int icp = 0; icp < 8; icp++) {
            uint32_t hp[4], lp[4];
#pragma unroll
            for (int jj = 0; jj < 2; jj++) {
                int ic = icp*8 + jj*4;
                float2 a0 = __ldg(xPb + (size_t)ic*HWs + o0);
                float2 a1 = __ldg(xPb + (size_t)ic*HWs + o1);
                float2 b0 = __ldg(xPb + (size_t)(ic+1)*HWs + o0);
                float2 b1 = __ldg(xPb + (size_t)(ic+1)*HWs + o1);
                float2 e0 = __ldg(xPb + (size_t)(ic+2)*HWs + o0);
                float2 e1 = __ldg(xPb + (size_t)(ic+2)*HWs + o1);
                float2 f0 = __ldg(xPb + (size_t)(ic+3)*HWs + o0);
                float2 f1 = __ldg(xPb + (size_t)(ic+3)*HWs + o1);
                float v0 = c00*a0.x + c01*a0.y + c10*a1.x + c11*a1.y;
                float v1 = c00*b0.x + c01*b0.y + c10*b1.x + c11*b1.y;
                float v2 = c00*e0.x + c01*e0.y + c10*e1.x + c11*e1.y;
                float v3 = c00*f0.x + c01*f0.y + c10*f1.x + c11*f1.y;
                uint32_t hh0, hh1;
                asm("cvt.rn.bf16x2.f32 %0, %1, %2;" : "=r"(hh0) : "f"(v1), "f"(v0));
                asm("cvt.rn.bf16x2.f32 %0, %1, %2;" : "=r"(hh1) : "f"(v3), "f"(v2));
                float l0 = v0 - __uint_as_float(hh0 << 16);
                float l1 = v1 - __uint_as_float(hh0 & 0xffff0000u);
                float l2 = v2 - __uint_as_float(hh1 << 16);
                float l3 = v3 - __uint_as_float(hh1 & 0xffff0000u);
                uint32_t ll0, ll1;
                asm("cvt.rn.bf16x2.f32 %0, %1, %2;" : "=r"(ll0) : "f"(l1), "f"(l0));
                asm("cvt.rn.bf16x2.f32 %0, %1, %2;" : "=r"(ll1) : "f"(l3), "f"(l2));
                hp[2*jj] = hh0; hp[2*jj+1] = hh1;
                lp[2*jj] = ll0; lp[2*jj+1] = ll1;
            }
            uint32_t off = ((uint32_t)(icp*16)) ^ swz;
            *(uint4*)(shi_row + off) = make_uint4(hp[0], hp[1], hp[2], hp[3]);
            *(uint4*)(slo_row + off) = make_uint4(lp[0], lp[1], lp[2], lp[3]);
        }
        __syncthreads();

        // ---- MMA: 4 k16-chunks x (2 m-tiles x 8 n-tiles) x 3 bf16x2 terms ----
#pragma unroll
        for (int kc = 0; kc < 4; kc++) {
            int colb = kc*32 + ab_colsl;
            uint32_t ah[2][4], al[2][4];
#pragma unroll
            for (int mt = 0; mt < 2; mt++) {
                int row = a_row0 + mt*16;
                uint32_t boff = (uint32_t)(row*128 + (colb ^ ((row & 7) << 4)));
                ldsm_x4(ah[mt], smem_base + SM_SHI + boff);
                ldsm_x4(al[mt], smem_base + SM_SLO + boff);
            }
#pragma unroll
            for (int ntp = 0; ntp < 4; ntp++) {
                int nrow = b_row0 + ntp*16;
                uint32_t boff = (uint32_t)(nrow*128 + (colb ^ ((nrow & 7) << 4)));
                uint32_t bh[4], bl[4];
                ldsm_x4(bh, smem_base + SM_WHI + boff);
                ldsm_x4(bl, smem_base + SM_WLO + boff);
#pragma unroll
                for (int mt = 0; mt < 2; mt++) {
                    mma_bf16(acc[mt][2*ntp  ], ah[mt], bh[0], bh[2]);
                    mma_bf16(acc[mt][2*ntp  ], ah[mt], bl[0], bl[2]);
                    mma_bf16(acc[mt][2*ntp  ], al[mt], bh[0], bh[2]);
                    mma_bf16(acc[mt][2*ntp+1], ah[mt], bh[1], bh[3]);
                    mma_bf16(acc[mt][2*ntp+1], ah[mt], bl[1], bl[3]);
                    mma_bf16(acc[mt][2*ntp+1], al[mt], bh[1], bh[3]);
                }
            }
        }
        __syncthreads();   // all warps done reading S/W before next tap overwrites
    }

    // ---- epilogue: fragment scatter to gmem (+bias) ----
    float* outg = out + (size_t)bg * CGc * HWs + hblk*4*64;
    const float* bbp = def_b + g*CGc;
#pragma unroll
    for (int mt = 0; mt < 2; mt++) {
        int row0  = wid*32 + mt*16 + (lane >> 2);
        int h_loc = row0 >> 6;
        int wp    = row0 & 63;
        float* p0 = outg + h_loc*64 + wp;
        float* p1 = p0 + 8;   // row0+8 stays in same 64-row band
#pragma unroll
        for (int nt = 0; nt < 8; nt++) {
            int oc0 = nt*8 + (lane & 3)*2;
            float bz0 = __ldg(bbp + oc0);
            float bz1 = __ldg(bbp + oc0 + 1);
            p0[(size_t)oc0*HWs]       = acc[mt][nt][0] + bz0;
            p0[(size_t)(oc0+1)*HWs]   = acc[mt][nt][1] + bz1;
            p1[(size_t)oc0*HWs]       = acc[mt][nt][2] + bz0;
            p1[(size_t)(oc0+1)*HWs]   = acc[mt][nt][3] + bz1;
        }
    }
}

// ---------------- launch ----------------
extern "C" void kernel_launch(void* const* d_in, const int* in_sizes, int n_in,
                              void* d_out, int out_size) {
    const float* x     = (const float*)d_in[0];
    const float* off_w = (const float*)d_in[1];
    const float* off_b = (const float*)d_in[2];
    const float* def_w = (const float*)d_in[3];
    const float* def_b = (const float*)d_in[4];
    float* out = (float*)d_out;

    cudaFuncSetAttribute(offset_kernel, cudaFuncAttributeMaxDynamicSharedMemorySize,
                         (12288 + 11520) * (int)sizeof(float));   // 95232 B
    cudaFuncSetAttribute(deform_kernel, cudaFuncAttributeMaxDynamicSharedMemorySize,
                         SM_TOTAL);                               // 81920 B

    prep_kernel<<<(GG*KK*CGc*CGc + 255) / 256, 256>>>(off_w, def_w);
    pair_kernel<<<BB*GG*CGc*HWs/256, 256>>>(x);
    offset_kernel<<<BB*GG*HH, 256, (12288 + 11520) * sizeof(float)>>>(x, off_b);
    deform_kernel<<<BB*GG*(HH/4), 256, SM_TOTAL>>>(def_b, out);
}

// round 10
// speedup vs baseline: 1.6263x; 1.2839x over previous
#include <cuda_runtime.h>
#include <cuda_bf16.h>
#include <math.h>
#include <stdint.h>

#define BB 16
#define GG 4
#define CGc 64
#define HH 64
#define WW 64
#define HWs 4096
#define KK 9

// ---------------- scratch (static; no allocation) ----------------
__device__ float g_off[BB*GG*18*HWs];                 // offsets [bg][c=2k+j][h][w]
__device__ float2 g_xP[BB*GG*CGc*HWs];                // x pairs: [bg][ic][y][x] = (v[x], v[x+1])  (134MB)
__device__ __nv_bfloat16 g_wbh[GG*KK*CGc*CGc];        // def_w bf16 hi, pre-SW128-swizzled rows [oc][ic]
__device__ __nv_bfloat16 g_wbl[GG*KK*CGc*CGc];        // def_w bf16 lo, same layout
__device__ __nv_bfloat16 g_owbh[GG*KK*32*CGc];        // off_w bf16 hi, SW128 rows [oc(32 pad)][ic]
__device__ __nv_bfloat16 g_owbl[GG*KK*32*CGc];        // off_w bf16 lo

#define SWZ128(off) ((off) ^ (((off) >> 3) & 0x70))

// ---------------- helpers ----------------
__device__ __forceinline__ uint32_t smem_u32(const void* p) {
    uint32_t a;
    asm("{ .reg .u64 t; cvta.to.shared.u64 t, %1; cvt.u32.u64 %0, t; }" : "=r"(a) : "l"(p));
    return a;
}
__device__ __forceinline__ void ldsm_x4(uint32_t* r, uint32_t addr) {
    asm volatile("ldmatrix.sync.aligned.m8n8.x4.shared.b16 {%0,%1,%2,%3}, [%4];"
        : "=r"(r[0]), "=r"(r[1]), "=r"(r[2]), "=r"(r[3]) : "r"(addr));
}
__device__ __forceinline__ void mma_bf16(float* d, const uint32_t* a, uint32_t b0, uint32_t b1) {
    asm volatile(
        "mma.sync.aligned.m16n8k16.row.col.f32.bf16.bf16.f32 "
        "{%0,%1,%2,%3}, {%4,%5,%6,%7}, {%8,%9}, {%0,%1,%2,%3};"
        : "+f"(d[0]), "+f"(d[1]), "+f"(d[2]), "+f"(d[3])
        : "r"(a[0]), "r"(a[1]), "r"(a[2]), "r"(a[3]), "r"(b0), "r"(b1));
}

// ---------------- prep: weight transforms ----------------
__global__ void prep_kernel(const float* __restrict__ off_w,
                            const float* __restrict__ def_w) {
    int idx = blockIdx.x * blockDim.x + threadIdx.x;
    const int n_w = GG*KK*CGc*CGc;    // 147456
    if (idx < n_w) {
        int ic = idx & 63;
        int oc = (idx >> 6) & 63;
        int gk = idx >> 12;           // g*9+k
        int k  = gk % KK;
        int g  = gk / KK;
        float w = def_w[((g*CGc + oc)*CGc + ic)*KK + k];
        __nv_bfloat16 hi = __float2bfloat16(w);
        float lo = w - __bfloat162float(hi);
        uint32_t sw = SWZ128((uint32_t)(oc*128 + ic*2));
        size_t base = (size_t)(g*KK + k) * CGc * CGc;
        g_wbh[base + sw/2] = hi;
        g_wbl[base + sw/2] = __float2bfloat16(lo);
    }
    const int n_ow = GG*KK*32*CGc;    // 73728  offset-conv weights, oc padded to 32
    if (idx < n_ow) {
        int ic = idx & 63;
        int oc = (idx >> 6) & 31;
        int gk = idx >> 11;           // g*9+k
        int k  = gk % KK;
        int g  = gk / KK;
        float w = (oc < 18) ? off_w[((g*18 + oc)*CGc + ic)*KK + k] : 0.0f;
        __nv_bfloat16 hi = __float2bfloat16(w);
        float lo = w - __bfloat162float(hi);
        uint32_t sw = SWZ128((uint32_t)(oc*128 + ic*2));
        size_t base = (size_t)(g*KK + k) * 32 * CGc;
        g_owbh[base + sw/2] = hi;
        g_owbl[base + sw/2] = __float2bfloat16(lo);
    }
}

// ---------------- pair build: xP[i] = (x[i], x[i+1 or clamp]) ----------------
__global__ void __launch_bounds__(256) pair_kernel(const float* __restrict__ x) {
    size_t i = (size_t)blockIdx.x * 256 + threadIdx.x;   // over BB*GG*CGc*HWs
    int xc = (int)(i & 63);
    float v  = x[i];
    float vn = (xc < 63) ? x[i + 1] : v;
    g_xP[i] = make_float2(v, vn);
}

// ---------------- offset conv via mma.sync: 64 -> 18(pad 32), 3x3 ----------------
// block = (b, g, hblk of 4 rows); 256 threads (8 warps)
// M=256 (4h x 64w), N=32 oc(pad), K per tap = 64 ic, 9 taps
#define OSM_SHI  0        // S hi [256 x 64] bf16 SW128 : 32768 B
#define OSM_SLO  32768    // S lo                       : 32768 B
#define OSM_WHI  65536    // W hi [32 x 64] bf16 SW128  :  4096 B
#define OSM_WLO  69632    // W lo                       :  4096 B
#define OSM_TOTAL 73728

extern __shared__ char osmem[];
__global__ void __launch_bounds__(256) offset_mma_kernel(const float* __restrict__ x,
                                                         const float* __restrict__ off_b) {
    char* sm = osmem;
    uint32_t smem_base = smem_u32(sm);
    int tid  = threadIdx.x;
    int wid  = tid >> 5;
    int lane = tid & 31;

    int bid  = blockIdx.x;
    int hblk = bid & 15;
    int g    = (bid >> 4) & 3;
    int b    = bid >> 6;
    int bg   = b*GG + g;

    int m    = tid;            // S-tile row this thread fills
    int r    = m >> 6;         // 0..3
    int wpos = m & 63;
    int h    = hblk*4 + r;

    const float* xb = x + (size_t)bg * CGc * HWs;

    char* shi_row = sm + OSM_SHI + m*128;
    char* slo_row = sm + OSM_SLO + m*128;
    uint32_t swz = (uint32_t)((m & 7) << 4);

    float acc[2][4][4];
#pragma unroll
    for (int mt = 0; mt < 2; mt++)
#pragma unroll
        for (int nt = 0; nt < 4; nt++)
#pragma unroll
            for (int q = 0; q < 4; q++) acc[mt][nt][q] = 0.0f;

    int a_row0   = wid*32 + (lane & 15);
    int ab_colsl = (lane >> 4) << 4;
    int b_row0   = ((lane >> 3) & 1)*8 + (lane & 7);

    for (int k = 0; k < KK; k++) {
        // ---- fill W tiles (pre-swizzled gmem -> linear copy, 4KB each) ----
        {
            const uint4* s1 = (const uint4*)(g_owbh + (size_t)(g*KK + k) * 32 * CGc);
            const uint4* s2 = (const uint4*)(g_owbl + (size_t)(g*KK + k) * 32 * CGc);
            ((uint4*)(sm + OSM_WHI))[tid] = s1[tid];
            ((uint4*)(sm + OSM_WLO))[tid] = s2[tid];
        }

        // ---- S fill: shifted x with zero padding (coalesced loads) ----
        int dy = k/3 - 1, dx = k%3 - 1;
        int y    = h + dy;
        int xcol = wpos + dx;
        bool valid = (y >= 0 && y < HH && xcol >= 0 && xcol < WW);
        const float* xs = xb + y*WW + xcol;   // + ic*HWs per channel
#pragma unroll
        for (int icp = 0; icp < 8; icp++) {
            uint32_t hp[4], lp[4];
#pragma unroll
            for (int jj = 0; jj < 2; jj++) {
                int ic = icp*8 + jj*4;
                float v0 = valid ? __ldg(xs + (size_t)(ic  )*HWs) : 0.0f;
                float v1 = valid ? __ldg(xs + (size_t)(ic+1)*HWs) : 0.0f;
                float v2 = valid ? __ldg(xs + (size_t)(ic+2)*HWs) : 0.0f;
                float v3 = valid ? __ldg(xs + (size_t)(ic+3)*HWs) : 0.0f;
                uint32_t hh0, hh1;
                asm("cvt.rn.bf16x2.f32 %0, %1, %2;" : "=r"(hh0) : "f"(v1), "f"(v0));
                asm("cvt.rn.bf16x2.f32 %0, %1, %2;" : "=r"(hh1) : "f"(v3), "f"(v2));
                float l0 = v0 - __uint_as_float(hh0 << 16);
                float l1 = v1 - __uint_as_float(hh0 & 0xffff0000u);
                float l2 = v2 - __uint_as_float(hh1 << 16);
                float l3 = v3 - __uint_as_float(hh1 & 0xffff0000u);
                uint32_t ll0, ll1;
                asm("cvt.rn.bf16x2.f32 %0, %1, %2;" : "=r"(ll0) : "f"(l1), "f"(l0));
                asm("cvt.rn.bf16x2.f32 %0, %1, %2;" : "=r"(ll1) : "f"(l3), "f"(l2));
                hp[2*jj] = hh0; hp[2*jj+1] = hh1;
                lp[2*jj] = ll0; lp[2*jj+1] = ll1;
            }
            uint32_t off = ((uint32_t)(icp*16)) ^ swz;
            *(uint4*)(shi_row + off) = make_uint4(hp[0], hp[1], hp[2], hp[3]);
            *(uint4*)(slo_row + off) = make_uint4(lp[0], lp[1], lp[2], lp[3]);
        }
        __syncthreads();

        // ---- MMA: 4 k16-chunks x (2 m-tiles x 4 n-tiles) x 3 bf16x2 terms ----
#pragma unroll
        for (int kc = 0; kc < 4; kc++) {
            int colb = kc*32 + ab_colsl;
            uint32_t ah[2][4], al[2][4];
#pragma unroll
            for (int mt = 0; mt < 2; mt++) {
                int row = a_row0 + mt*16;
                uint32_t boff = (uint32_t)(row*128 + (colb ^ ((row & 7) << 4)));
                ldsm_x4(ah[mt], smem_base + OSM_SHI + boff);
                ldsm_x4(al[mt], smem_base + OSM_SLO + boff);
            }
#pragma unroll
            for (int ntp = 0; ntp < 2; ntp++) {
                int nrow = b_row0 + ntp*16;
                uint32_t boff = (uint32_t)(nrow*128 + (colb ^ ((nrow & 7) << 4)));
                uint32_t bh[4], bl[4];
                ldsm_x4(bh, smem_base + OSM_WHI + boff);
                ldsm_x4(bl, smem_base + OSM_WLO + boff);
#pragma unroll
                for (int mt = 0; mt < 2; mt++) {
                    mma_bf16(acc[mt][2*ntp  ], ah[mt], bh[0], bh[2]);
                    mma_bf16(acc[mt][2*ntp  ], ah[mt], bl[0], bl[2]);
                    mma_bf16(acc[mt][2*ntp  ], al[mt], bh[0], bh[2]);
                    mma_bf16(acc[mt][2*ntp+1], ah[mt], bh[1], bh[3]);
                    mma_bf16(acc[mt][2*ntp+1], ah[mt], bl[1], bl[3]);
                    mma_bf16(acc[mt][2*ntp+1], al[mt], bh[1], bh[3]);
                }
            }
        }
        __syncthreads();
    }

    // ---- epilogue: write offsets (c < 18) + bias ----
    float* og = g_off + (size_t)bg * 18 * HWs + hblk*4*64;
    const float* obp = off_b + g*18;
#pragma unroll
    for (int mt = 0; mt < 2; mt++) {
        int row0  = wid*32 + mt*16 + (lane >> 2);
        int h_loc = row0 >> 6;
        int wp    = row0 & 63;
        float* p0 = og + h_loc*64 + wp;
        float* p1 = p0 + 8;
#pragma unroll
        for (int nt = 0; nt < 4; nt++) {
            int c0 = nt*8 + (lane & 3)*2;
            if (c0 < 18) {
                float bz0 = __ldg(obp + c0);
                float bz1 = __ldg(obp + c0 + 1);
                p0[(size_t)c0*HWs]     = acc[mt][nt][0] + bz0;
                p0[(size_t)(c0+1)*HWs] = acc[mt][nt][1] + bz1;
                p1[(size_t)c0*HWs]     = acc[mt][nt][2] + bz0;
                p1[(size_t)(c0+1)*HWs] = acc[mt][nt][3] + bz1;
            }
        }
    }
}

// ---------------- deformable conv: mma.sync bf16x2 GEMM (UNCHANGED from R9 pass) ----------------
// block = (b, g, hblk of 4 rows); 256 threads (8 warps)
// M=256 (4h x 64w), N=64 oc, K per tap = 64 ic, 9 taps
#define SM_SHI  0        // S hi [256 x 64] bf16 SW128 : 32768 B
#define SM_SLO  32768    // S lo                       : 32768 B
#define SM_WHI  65536    // W hi [64 x 64] bf16 SW128  :  8192 B
#define SM_WLO  73728    // W lo                       :  8192 B
#define SM_TOTAL 81920

extern __shared__ char smem2[];
__global__ void __launch_bounds__(256) deform_kernel(const float* __restrict__ def_b,
                                                     float* __restrict__ out) {
    char* sm = smem2;
    uint32_t smem_base = smem_u32(sm);
    int tid  = threadIdx.x;
    int wid  = tid >> 5;
    int lane = tid & 31;

    int bid  = blockIdx.x;
    int hblk = bid & 15;
    int g    = (bid >> 4) & 3;
    int b    = bid >> 6;
    int bg   = b*GG + g;

    int m    = tid;            // S-tile row this thread gathers
    int r    = m >> 6;         // 0..3
    int wpos = m & 63;
    int h    = hblk*4 + r;

    const float2* xPb = g_xP + (size_t)bg * CGc * HWs;
    const float* offp = g_off + (size_t)bg * 18 * HWs + h*64 + wpos;

    char* shi_row = sm + SM_SHI + m*128;
    char* slo_row = sm + SM_SLO + m*128;
    uint32_t swz = (uint32_t)((m & 7) << 4);

    float acc[2][8][4];
#pragma unroll
    for (int mt = 0; mt < 2; mt++)
#pragma unroll
        for (int nt = 0; nt < 8; nt++)
#pragma unroll
            for (int q = 0; q < 4; q++) acc[mt][nt][q] = 0.0f;

    int a_row0   = wid*32 + (lane & 15);
    int ab_colsl = (lane >> 4) << 4;
    int b_row0   = ((lane >> 3) & 1)*8 + (lane & 7);

    for (int k = 0; k < KK; k++) {
        // ---- fill W tiles (pre-swizzled gmem -> linear copy) ----
        {
            const uint4* s1 = (const uint4*)(g_wbh + (size_t)(g*KK + k) * CGc * CGc);
            const uint4* s2 = (const uint4*)(g_wbl + (size_t)(g*KK + k) * CGc * CGc);
            uint4* d1 = (uint4*)(sm + SM_WHI);
            uint4* d2 = (uint4*)(sm + SM_WLO);
#pragma unroll
            for (int i = 0; i < 2; i++) {
                d1[tid + i*256] = s1[tid + i*256];
                d2[tid + i*256] = s2[tid + i*256];
            }
        }

        // ---- per-thread bilinear corner precompute ----
        float dy = __ldg(offp + (2*k    )*HWs);
        float dx = __ldg(offp + (2*k + 1)*HWs);
        float py = dy + (float)(k/3 - 1) + (float)h;
        float px = dx + (float)(k%3 - 1) + (float)wpos;
        float fy = floorf(py), fx = floorf(px);
        float wy = py - fy,    wx = px - fx;
        int y0 = (int)fy, x0 = (int)fx;
        int y1 = y0 + 1,  x1 = x0 + 1;
        float vy0 = (y0 >= 0 && y0 < HH) ? 1.f : 0.f;
        float vy1 = (y1 >= 0 && y1 < HH) ? 1.f : 0.f;
        float vx0 = (x0 >= 0 && x0 < WW) ? 1.f : 0.f;
        float vx1 = (x1 >= 0 && x1 < WW) ? 1.f : 0.f;
        float c00 = (1.f-wy)*(1.f-wx) * vy0 * vx0;
        float c01 = (1.f-wy)*wx       * vy0 * vx1;
        float c10 = wy*(1.f-wx)       * vy1 * vx0;
        float c11 = wy*wx             * vy1 * vx1;
        if (x0 < 0) { c00 = c01; c01 = 0.f; c10 = c11; c11 = 0.f; }
        int xl  = min(max(x0,0),WW-1);
        int y0c = min(max(y0,0),HH-1), y1c = min(max(y1,0),HH-1);
        int o0 = y0c*WW + xl;
        int o1 = y1c*WW + xl;

        // ---- gather (paired LDG.64) + bf16 hi/lo split into S tiles ----
#pragma unroll
        for (int icp = 0; icp < 8; icp++) {
            uint32_t hp[4], lp[4];
#pragma unroll
            for (int jj = 0; jj < 2; jj++) {
                int ic = icp*8 + jj*4;
                float2 a0 = __ldg(xPb + (size_t)ic*HWs + o0);
                float2 a1 = __ldg(xPb + (size_t)ic*HWs + o1);
                float2 b0 = __ldg(xPb + (size_t)(ic+1)*HWs + o0);
                float2 b1 = __ldg(xPb + (size_t)(ic+1)*HWs + o1);
                float2 e0 = __ldg(xPb + (size_t)(ic+2)*HWs + o0);
                float2 e1 = __ldg(xPb + (size_t)(ic+2)*HWs + o1);
                float2 f0 = __ldg(xPb + (size_t)(ic+3)*HWs + o0);
                float2 f1 = __ldg(xPb + (size_t)(ic+3)*HWs + o1);
                float v0 = c00*a0.x + c01*a0.y + c10*a1.x + c11*a1.y;
                float v1 = c00*b0.x + c01*b0.y + c10*b1.x + c11*b1.y;
                float v2 = c00*e0.x + c01*e0.y + c10*e1.x + c11*e1.y;
                float v3 = c00*f0.x + c01*f0.y + c10*f1.x + c11*f1.y;
                uint32_t hh0, hh1;
                asm("cvt.rn.bf16x2.f32 %0, %1, %2;" : "=r"(hh0) : "f"(v1), "f"(v0));
                asm("cvt.rn.bf16x2.f32 %0, %1, %2;" : "=r"(hh1) : "f"(v3), "f"(v2));
                float l0 = v0 - __uint_as_float(hh0 << 16);
                float l1 = v1 - __uint_as_float(hh0 & 0xffff0000u);
                float l2 = v2 - __uint_as_float(hh1 << 16);
                float l3 = v3 - __uint_as_float(hh1 & 0xffff0000u);
                uint32_t ll0, ll1;
                asm("cvt.rn.bf16x2.f32 %0, %1, %2;" : "=r"(ll0) : "f"(l1), "f"(l0));
                asm("cvt.rn.bf16x2.f32 %0, %1, %2;" : "=r"(ll1) : "f"(l3), "f"(l2));
                hp[2*jj] = hh0; hp[2*jj+1] = hh1;
                lp[2*jj] = ll0; lp[2*jj+1] = ll1;
            }
            uint32_t off = ((uint32_t)(icp*16)) ^ swz;
            *(uint4*)(shi_row + off) = make_uint4(hp[0], hp[1], hp[2], hp[3]);
            *(uint4*)(slo_row + off) = make_uint4(lp[0], lp[1], lp[2], lp[3]);
        }
        __syncthreads();

        // ---- MMA: 4 k16-chunks x (2 m-tiles x 8 n-tiles) x 3 bf16x2 terms ----
#pragma unroll
        for (int kc = 0; kc < 4; kc++) {
            int colb = kc*32 + ab_colsl;
            uint32_t ah[2][4], al[2][4];
#pragma unroll
            for (int mt = 0; mt < 2; mt++) {
                int row = a_row0 + mt*16;
                uint32_t boff = (uint32_t)(row*128 + (colb ^ ((row & 7) << 4)));
                ldsm_x4(ah[mt], smem_base + SM_SHI + boff);
                ldsm_x4(al[mt], smem_base + SM_SLO + boff);
            }
#pragma unroll
            for (int ntp = 0; ntp < 4; ntp++) {
                int nrow = b_row0 + ntp*16;
                uint32_t boff = (uint32_t)(nrow*128 + (colb ^ ((nrow & 7) << 4)));
                uint32_t bh[4], bl[4];
                ldsm_x4(bh, smem_base + SM_WHI + boff);
                ldsm_x4(bl, smem_base + SM_WLO + boff);
#pragma unroll
                for (int mt = 0; mt < 2; mt++) {
                    mma_bf16(acc[mt][2*ntp  ], ah[mt], bh[0], bh[2]);
                    mma_bf16(acc[mt][2*ntp  ], ah[mt], bl[0], bl[2]);
                    mma_bf16(acc[mt][2*ntp  ], al[mt], bh[0], bh[2]);
                    mma_bf16(acc[mt][2*ntp+1], ah[mt], bh[1], bh[3]);
                    mma_bf16(acc[mt][2*ntp+1], ah[mt], bl[1], bl[3]);
                    mma_bf16(acc[mt][2*ntp+1], al[mt], bh[1], bh[3]);
                }
            }
        }
        __syncthreads();
    }

    // ---- epilogue: fragment scatter to gmem (+bias) ----
    float* outg = out + (size_t)bg * CGc * HWs + hblk*4*64;
    const float* bbp = def_b + g*CGc;
#pragma unroll
    for (int mt = 0; mt < 2; mt++) {
        int row0  = wid*32 + mt*16 + (lane >> 2);
        int h_loc = row0 >> 6;
        int wp    = row0 & 63;
        float* p0 = outg + h_loc*64 + wp;
        float* p1 = p0 + 8;
#pragma unroll
        for (int nt = 0; nt < 8; nt++) {
            int oc0 = nt*8 + (lane & 3)*2;
            float bz0 = __ldg(bbp + oc0);
            float bz1 = __ldg(bbp + oc0 + 1);
            p0[(size_t)oc0*HWs]       = acc[mt][nt][0] + bz0;
            p0[(size_t)(oc0+1)*HWs]   = acc[mt][nt][1] + bz1;
            p1[(size_t)oc0*HWs]       = acc[mt][nt][2] + bz0;
            p1[(size_t)(oc0+1)*HWs]   = acc[mt][nt][3] + bz1;
        }
    }
}

// ---------------- launch ----------------
extern "C" void kernel_launch(void* const* d_in, const int* in_sizes, int n_in,
                              void* d_out, int out_size) {
    const float* x     = (const float*)d_in[0];
    const float* off_w = (const float*)d_in[1];
    const float* off_b = (const float*)d_in[2];
    const float* def_w = (const float*)d_in[3];
    const float* def_b = (const float*)d_in[4];
    float* out = (float*)d_out;

    cudaFuncSetAttribute(offset_mma_kernel, cudaFuncAttributeMaxDynamicSharedMemorySize,
                         OSM_TOTAL);                              // 73728 B
    cudaFuncSetAttribute(deform_kernel, cudaFuncAttributeMaxDynamicSharedMemorySize,
                         SM_TOTAL);                               // 81920 B

    prep_kernel<<<(GG*KK*CGc*CGc + 255) / 256, 256>>>(off_w, def_w);
    pair_kernel<<<BB*GG*CGc*HWs/256, 256>>>(x);
    offset_mma_kernel<<<BB*GG*(HH/4), 256, OSM_TOTAL>>>(x, off_b);
    deform_kernel<<<BB*GG*(HH/4), 256, SM_TOTAL>>>(def_b, out);
}